// round 14
// baseline (speedup 1.0000x reference)
#include <cuda_runtime.h>
#include <cuda_fp16.h>
#include <math.h>
#include <stdint.h>

#define EPSV 1e-5f

// ---------------- scratch (allocation-free: device globals) ----------------
__device__ float    g_ss  [64*1024];
__device__ unsigned short g_xt [64*512*256];   // fp16 x, [b][l][ci]
__device__ unsigned short g_h2 [64*512*512];   // fp16 conv0 out, [b][l][co]
__device__ unsigned short g_xln[64*512*512];   // fp16 LN(out), [b][t][c]
__device__ unsigned short g_cn [64*77*768];    // fp16 LN(cond), [b][n][ci]
__device__ float    g_k   [64*512*77];
__device__ float    g_v   [64*512*77];
__device__ float    g_attn[64*8*64*64];
// fragment-permuted fp16 weight copies (u32 = half2 k-pairs)
__device__ uint32_t g_w0[512*256*5/2];
__device__ uint32_t g_w1[512*512*5/2];
__device__ uint32_t g_wr[512*256/2];
__device__ uint32_t g_wq[512*512/2];
__device__ uint32_t g_wk[512*768/2];
__device__ uint32_t g_wv[512*768/2];

// fast mish
__device__ __forceinline__ float mishf(float x){
    float xc = fminf(x, 15.f);
    float e  = __expf(xc);
    float u  = 1.f + e;
    float u2 = u * u;
    return x * __fdividef(u2 - 1.f, u2 + 1.f);
}

// ---------------- fp16 mma helpers ------------------------------------------
__device__ __forceinline__ void mma_f16(float* c, uint4 a, uint32_t b0, uint32_t b1){
    asm("mma.sync.aligned.m16n8k16.row.col.f32.f16.f16.f32 "
        "{%0,%1,%2,%3}, {%4,%5,%6,%7}, {%8,%9}, {%0,%1,%2,%3};"
        : "+f"(c[0]), "+f"(c[1]), "+f"(c[2]), "+f"(c[3])
        : "r"(a.x), "r"(a.y), "r"(a.z), "r"(a.w), "r"(b0), "r"(b1));
}
__device__ __forceinline__ void ldsm_x4(uint32_t &r0, uint32_t &r1, uint32_t &r2,
                                        uint32_t &r3, uint32_t addr){
    asm volatile("ldmatrix.sync.aligned.m8n8.x4.shared.b16 {%0,%1,%2,%3}, [%4];"
                 : "=r"(r0), "=r"(r1), "=r"(r2), "=r"(r3) : "r"(addr));
}

// ---------------- cp.async helpers -------------------------------------------
__device__ __forceinline__ void cp16p(uint32_t dst, const void* src, bool pred){
    int sz = pred ? 16 : 0;
    asm volatile("cp.async.cg.shared.global [%0], [%1], 16, %2;"
                 :: "r"(dst), "l"(src), "r"(sz));
}
__device__ __forceinline__ void cp16(uint32_t dst, const void* src){
    asm volatile("cp.async.cg.shared.global [%0], [%1], 16;" :: "r"(dst), "l"(src));
}
__device__ __forceinline__ void cp_commit(){
    asm volatile("cp.async.commit_group;");
}
template<int N>
__device__ __forceinline__ void cp_wait(){
    asm volatile("cp.async.wait_group %0;" :: "n"(N));
}

// ---------------- weight permutation helper ----------------------------------
__device__ __forceinline__ void wperm1(const float* __restrict__ w, uint32_t* __restrict__ dst,
                                       int f, int CIN, int TAPS){
    int NCH = CIN/16;
    int j    = f & 3;
    int rem  = f >> 2;
    int lane = rem & 31;  rem >>= 5;
    int tap  = rem % TAPS; rem /= TAPS;
    int s    = rem & 3;   rem >>= 2;
    int ch   = rem % NCH;
    int cb   = rem / NCH;
    int qr = lane >> 2, qc = lane & 3;
    int co = cb*64 + s*16 + qr + (j & 1)*8;
    int ci = ch*16 + 2*qc + (j >> 1)*8;
    float w0 = w[((size_t)co*CIN + ci    )*TAPS + tap];
    float w1 = w[((size_t)co*CIN + ci + 1)*TAPS + tap];
    __half2 h = __floats2half2_rn(w0, w1);
    dst[f] = *(uint32_t*)&h;
}

// ---------------- mega-producer: xpose | wprep | ss | cn ----------------------
// grid layout: [0,8192) xpose, [8192,8960) wprep, [8960,9024) ss, [9024,13952) cn
__global__ void k_prod(const float* __restrict__ x,
                       const float* __restrict__ t, const float* __restrict__ tmw,
                       const float* __restrict__ tmb,
                       const float* __restrict__ cond, const float* __restrict__ cg,
                       const float* __restrict__ cb, const int* __restrict__ cidx,
                       const float* w0s, const float* w1s, const float* wrs,
                       const float* wqs, const float* wks, const float* wvs){
    __shared__ float t32[32][33];
    __shared__ float tm[512];
    __shared__ float row[768];
    __shared__ float wsum[8], wsq[8];
    const int f = blockIdx.x, tid = threadIdx.x;

    if (f < 8192){
        int lx = f & 15, cy = (f >> 4) & 7, b = f >> 7;
        int c0 = cy*32, l0 = lx*32;
        int tx = tid & 31, ty = tid >> 5;
        #pragma unroll
        for (int i = ty; i < 32; i += 8)
            t32[i][tx] = x[((size_t)b*256 + c0 + i)*512 + l0 + tx];
        __syncthreads();
        #pragma unroll
        for (int i = ty; i < 32; i += 8){
            __half h = __float2half(t32[tx][i]);
            g_xt[((size_t)b*512 + l0 + i)*256 + c0 + tx] = *(unsigned short*)&h;
        }
    } else if (f < 8960){
        const int n0 = 512*256*5/2, n1 = 512*512*5/2, n2 = 512*256/2;
        const int n3 = 512*512/2,   n4 = 512*768/2,   n5 = 512*768/2;
        const int c0 = n0, c1 = c0+n1, c2 = c1+n2, c3 = c2+n3, c4 = c3+n4, c5 = c4+n5;
        for (int i = (f - 8192)*256 + tid; i < c5; i += 768*256){
            if      (i < c0) wperm1(w0s, g_w0, i,      256, 5);
            else if (i < c1) wperm1(w1s, g_w1, i - c0, 512, 5);
            else if (i < c2) wperm1(wrs, g_wr, i - c1, 256, 1);
            else if (i < c3) wperm1(wqs, g_wq, i - c2, 512, 1);
            else if (i < c4) wperm1(wks, g_wk, i - c3, 768, 1);
            else             wperm1(wvs, g_wv, i - c4, 768, 1);
        }
    } else if (f < 9024){
        int b = f - 8960;
        for (int i = tid; i < 512; i += 256) tm[i] = mishf(t[b*512 + i]);
        __syncthreads();
        for (int o = tid; o < 1024; o += 256){
            const float* wr = tmw + (size_t)o * 512;
            float acc = tmb[o];
            #pragma unroll 8
            for (int i = 0; i < 512; i++) acc = fmaf(tm[i], wr[i], acc);
            g_ss[b*1024 + o] = acc;
        }
    } else {
        int g = f - 9024;
        int n = g % 77, b = g / 77;
        int bi = cidx[b];
        int lane = tid & 31, w = tid >> 5;
        const float* src = cond + ((size_t)bi*77 + n)*768;
        float s = 0.f, q = 0.f;
        for (int i = tid; i < 768; i += 256){ float v = src[i]; row[i] = v; s += v; q += v*v; }
        #pragma unroll
        for (int o = 16; o; o >>= 1){ s += __shfl_xor_sync(0xffffffffu, s, o); q += __shfl_xor_sync(0xffffffffu, q, o); }
        if (lane == 0){ wsum[w] = s; wsq[w] = q; }
        __syncthreads();
        if (tid == 0){
            float S = 0.f, Q = 0.f;
            #pragma unroll
            for (int i = 0; i < 8; i++){ S += wsum[i]; Q += wsq[i]; }
            float m = S * (1.f/768.f); float var = Q * (1.f/768.f) - m*m;
            wsum[0] = m; wsq[0] = rsqrtf(var + EPSV);
        }
        __syncthreads();
        float m = wsum[0], r = wsq[0];
        for (int i = tid; i < 768; i += 256){
            __half h = __float2half((row[i] - m) * r * cg[i] + cb[i]);
            g_cn[((size_t)b*77 + n)*768 + i] = *(unsigned short*)&h;
        }
    }
}

// ---------------- conv1d as implicit GEMM on fp16 tensor cores ---------------
// (exact R12 kernel — signature and body unchanged)
// MODE 0: plain bias (fp32 out) | 1: +GN+FiLM+mish (fp16 [l][co] out)
// MODE 2: +GN+mish+res add (fp32) | 3: +softmax(64 rows) + y=q@attn RMW into out
template<int CIN, int TAPS, int PAD, int MODE>
__global__ void k_conv(const unsigned short* __restrict__ in, const uint32_t* __restrict__ w,
                       const float* __restrict__ bias, float* __restrict__ out, int L,
                       const float* __restrict__ gg, const float* __restrict__ gb,
                       const int* __restrict__ cidx){
    constexpr int NTILE = 128;
    constexpr int LWD = NTILE + TAPS - 1;   // xs rows (n)
    constexpr int KST = 24;                 // halves per xs row (16 + 8 pad)
    constexpr int XSU = LWD*(KST/2);        // xs u32
    constexpr int WSU = 512*TAPS;           // ws u32 per chunk
    constexpr int CHUNK = XSU + WSU;
    constexpr int EST = 132;
    extern __shared__ __align__(16) uint32_t smu[];
    __shared__ float red0[256], red1[256];
    __shared__ float stA[128], stB[128];
    __shared__ float rg[64], rb[64], rsc[64], rsh[64];

    const int l0 = blockIdx.x*NTILE, co0 = blockIdx.y*64, b = blockIdx.z;
    const int COUT = gridDim.y*64;
    const int tid = threadIdx.x, lane = tid & 31, wid = tid >> 5;
    const int wn = wid*16;
    const int qr = lane >> 2, qc = lane & 3;
    const uint32_t smaddr = (uint32_t)__cvta_generic_to_shared(smu);
    const int NCH = CIN/16;

    float acc[4][2][4];
    #pragma unroll
    for (int s = 0; s < 4; s++)
        #pragma unroll
        for (int ni = 0; ni < 2; ni++)
            #pragma unroll
            for (int r = 0; r < 4; r++) acc[s][ni][r] = 0.f;

    const unsigned short* inb = in + (size_t)b*L*CIN;
    const uint32_t* wblk = w + ((size_t)blockIdx.y*NCH)*WSU;

    auto fill = [&](int ch){
        uint32_t base = smaddr + (uint32_t)(ch % 3)*CHUNK*4;
        const int ci0 = ch*16;
        for (int idx = tid; idx < LWD*2; idx += 256){
            int row = idx >> 1, part = idx & 1;
            int l = l0 + row - PAD;
            bool ok = (l >= 0 && l < L);
            const unsigned short* src = inb + (size_t)(ok ? l : 0)*CIN + ci0 + part*8;
            cp16p(base + (row*KST + part*8)*2, src, ok);
        }
        uint32_t wsA = base + XSU*4;
        const uint32_t* wchunk = wblk + (size_t)ch*WSU;
        for (int idx = tid; idx < WSU/4; idx += 256)
            cp16(wsA + idx*16, wchunk + idx*4);
    };

    fill(0); cp_commit();
    if (NCH > 1) fill(1);
    cp_commit();

    for (int ch = 0; ch < NCH; ch++){
        if (ch + 2 < NCH) fill(ch + 2);
        cp_commit();
        cp_wait<2>();
        __syncthreads();

        const uint32_t xs_b = smaddr + (uint32_t)(ch % 3)*CHUNK*4;
        const uint32_t* wp = smu + (ch % 3)*CHUNK + XSU;

        #pragma unroll
        for (int tap = 0; tap < TAPS; tap++){
            uint4 A[4];
            #pragma unroll
            for (int s = 0; s < 4; s++)
                A[s] = *(const uint4*)&wp[((s*TAPS + tap)*32 + lane)*4];
            int row = wn + tap + (lane & 7) + ((lane >> 4) << 3);
            uint32_t addr = xs_b + ((uint32_t)row*KST + ((lane >> 3) & 1)*8)*2;
            uint32_t b0, b1, b2, b3;
            ldsm_x4(b0, b1, b2, b3, addr);
            #pragma unroll
            for (int s = 0; s < 4; s++){
                mma_f16(acc[s][0], A[s], b0, b1);
                mma_f16(acc[s][1], A[s], b2, b3);
            }
        }
        __syncthreads();
    }

    if (MODE == 0){
        #pragma unroll
        for (int s = 0; s < 4; s++){
            int r0 = co0 + s*16 + qr;
            float b0 = bias[r0], b1 = bias[r0 + 8];
            #pragma unroll
            for (int ni = 0; ni < 2; ni++){
                int c0 = l0 + wn + ni*8 + 2*qc;
                float* C = acc[s][ni];
                if (((L & 1) == 0) && (c0 + 1) < L){
                    *(float2*)&out[((size_t)b*COUT + r0    )*L + c0] = make_float2(C[0]+b0, C[1]+b0);
                    *(float2*)&out[((size_t)b*COUT + r0 + 8)*L + c0] = make_float2(C[2]+b1, C[3]+b1);
                } else {
                    if (c0 < L){
                        out[((size_t)b*COUT + r0    )*L + c0] = C[0] + b0;
                        out[((size_t)b*COUT + r0 + 8)*L + c0] = C[2] + b1;
                    }
                    if (c0 + 1 < L){
                        out[((size_t)b*COUT + r0    )*L + c0 + 1] = C[1] + b0;
                        out[((size_t)b*COUT + r0 + 8)*L + c0 + 1] = C[3] + b1;
                    }
                }
            }
        }
        return;
    }

    // ---- fused epilogue (full 64x128 tile; L == 512 here) ----
    float* et = (float*)smu;
    #pragma unroll
    for (int s = 0; s < 4; s++){
        int r0 = s*16 + qr;
        float b0 = bias[co0 + r0], b1 = bias[co0 + r0 + 8];
        #pragma unroll
        for (int ni = 0; ni < 2; ni++){
            int c0 = wn + ni*8 + 2*qc;
            float* C = acc[s][ni];
            *(float2*)&et[ r0     *EST + c0] = make_float2(C[0]+b0, C[1]+b0);
            *(float2*)&et[(r0 + 8)*EST + c0] = make_float2(C[2]+b1, C[3]+b1);
        }
    }
    if ((MODE == 1 || MODE == 2) && tid < 64){
        rg[tid] = gg[co0 + tid]; rb[tid] = gb[co0 + tid];
        if (MODE == 1){
            rsc[tid] = g_ss[b*1024 + co0 + tid];
            rsh[tid] = g_ss[b*1024 + 512 + co0 + tid];
        }
    }
    __syncthreads();

    const int c = tid & 127, half = tid >> 7;
    if (MODE == 1 || MODE == 2){
        float s = 0.f, q = 0.f;
        #pragma unroll
        for (int r = 0; r < 32; r++){
            float v = et[(half*32 + r)*EST + c];
            s += v; q += v*v;
        }
        red0[tid] = s; red1[tid] = q;
        __syncthreads();
        if (tid < 128){
            float S = red0[tid] + red0[tid + 128];
            float Q = red1[tid] + red1[tid + 128];
            float m = S * (1.f/64.f);
            stA[tid] = m;
            stB[tid] = rsqrtf(Q * (1.f/64.f) - m*m + EPSV);
        }
        __syncthreads();
    } else {
        float m = -1e30f;
        #pragma unroll
        for (int r = 0; r < 32; r++) m = fmaxf(m, et[(half*32 + r)*EST + c]);
        red0[tid] = m;
        __syncthreads();
        if (tid < 128) stA[tid] = fmaxf(red0[tid], red0[tid + 128]);
        __syncthreads();
        float s = 0.f;
        #pragma unroll
        for (int r = 0; r < 32; r++) s += __expf(et[(half*32 + r)*EST + c] - stA[c]);
        red1[tid] = s;
        __syncthreads();
        if (tid < 128) stB[tid] = 1.f / (red1[tid] + red1[tid + 128]);
        __syncthreads();
    }

    if (MODE == 1){
        unsigned short* oh = (unsigned short*)out;
        #pragma unroll 4
        for (int kk = 0; kk < 32; kk++){
            int idx = kk*256 + tid;
            int cc = idx >> 6, r = idx & 63;
            float v = et[r*EST + cc];
            v = (v - stA[cc]) * stB[cc] * rg[r] + rb[r];
            v = v * (1.f + rsc[r]) + rsh[r];
            __half h = __float2half(mishf(v));
            oh[((size_t)b*512 + l0 + cc)*COUT + co0 + r] = *(unsigned short*)&h;
        }
    } else if (MODE == 2){
        #pragma unroll 4
        for (int kk = 0; kk < 32; kk++){
            int idx = kk*256 + tid;
            int r = idx >> 7, cc = idx & 127;
            float v = et[r*EST + cc];
            size_t gidx = ((size_t)b*COUT + co0 + r)*L + l0 + cc;
            v = (v - stA[cc]) * stB[cc] * rg[r] + rb[r];
            out[gidx] = mishf(v) + out[gidx];
        }
    } else {
        // MODE 3: softmax over head-dim rows in place, then y = q@attn, RMW out
        float* asf = et + 64*EST;           // [64][68]
        #pragma unroll 4
        for (int kk = 0; kk < 32; kk++){
            int idx = kk*256 + tid;
            int r = idx >> 7, cc = idx & 127;
            et[r*EST + cc] = __expf(et[r*EST + cc] - stA[cc]) * stB[cc];
        }
        const int h = blockIdx.y;
        for (int idx = tid; idx < 64*64; idx += 256){
            int r = idx >> 6, cc = idx & 63;
            asf[r*68 + cc] = g_attn[(((size_t)(b*8 + h))*64 + r)*64 + cc];
        }
        __syncthreads();

        const int tx = tid & 15, ty = tid >> 4;
        float yacc[4][8];
        #pragma unroll
        for (int i = 0; i < 4; i++)
            #pragma unroll
            for (int j = 0; j < 8; j++) yacc[i][j] = 0.f;
        for (int d = 0; d < 64; d++){
            float4 q0 = *(const float4*)&et[d*EST + tx*8];
            float4 q1 = *(const float4*)&et[d*EST + tx*8 + 4];
            float qr8[8] = {q0.x,q0.y,q0.z,q0.w,q1.x,q1.y,q1.z,q1.w};
            float ar[4];
            #pragma unroll
            for (int i = 0; i < 4; i++) ar[i] = asf[d*68 + ty*4 + i];
            #pragma unroll
            for (int i = 0; i < 4; i++)
                #pragma unroll
                for (int j = 0; j < 8; j++) yacc[i][j] = fmaf(ar[i], qr8[j], yacc[i][j]);
        }
        const int bi = cidx[b];
        #pragma unroll
        for (int i = 0; i < 4; i++){
            int chn = co0 + ty*4 + i;
            float* dst = &out[((size_t)bi*512 + chn)*512 + l0 + tx*8];
            float4 o0 = *(float4*)dst;
            float4 o1 = *(float4*)(dst + 4);
            o0.x += yacc[i][0]; o0.y += yacc[i][1]; o0.z += yacc[i][2]; o0.w += yacc[i][3];
            o1.x += yacc[i][4]; o1.y += yacc[i][5]; o1.z += yacc[i][6]; o1.w += yacc[i][7];
            *(float4*)dst = o0;
            *(float4*)(dst + 4) = o1;
        }
    }
}

// ---------------- LN over channels -> g_xln fp16 [b][t][c], single gmem read -
__global__ void k_xln(const float* __restrict__ out, const float* __restrict__ gg,
                      const float* __restrict__ gb, const int* __restrict__ cidx,
                      unsigned short* __restrict__ dst){
    extern __shared__ float cache[];        // [64][513]
    __shared__ float sm_s[4][64], sm_q[4][64];
    __shared__ float m_[64], r_[64];
    __shared__ float sg[512], sb[512];
    int b = blockIdx.y, t0 = blockIdx.x*64;
    int bi = cidx[b];
    const float* src = out + (size_t)bi*512*512;
    int tid = threadIdx.x;
    int tl = tid & 63, seg = tid >> 6;
    for (int i = tid; i < 512; i += 256){ sg[i] = gg[i]; sb[i] = gb[i]; }
    float s = 0.f, q = 0.f;
    for (int c = seg; c < 512; c += 4){
        float v = src[(size_t)c*512 + t0 + tl];
        cache[tl*513 + c] = v;
        s += v; q += v*v;
    }
    sm_s[seg][tl] = s; sm_q[seg][tl] = q;
    __syncthreads();
    if (tid < 64){
        float S = sm_s[0][tid]+sm_s[1][tid]+sm_s[2][tid]+sm_s[3][tid];
        float Q = sm_q[0][tid]+sm_q[1][tid]+sm_q[2][tid]+sm_q[3][tid];
        float m = S * (1.f/512.f);
        m_[tid] = m;
        r_[tid] = rsqrtf(Q * (1.f/512.f) - m*m + EPSV);
    }
    __syncthreads();
    for (int idx = tid; idx < 64*512; idx += 256){
        int t = idx >> 9, c = idx & 511;
        float v = cache[t*513 + c];
        __half h = __float2half((v - m_[t]) * r_[t] * sg[c] + sb[c]);
        dst[((size_t)b*512 + t0 + t)*512 + c] = *(unsigned short*)&h;
    }
}

// ---------------- attn: k-softmax (over n) + attn = k^T v per (b,h) ----------
__global__ void k_attn(const float* __restrict__ kbuf, const float* __restrict__ vbuf){
    __shared__ float ks[64][80], vs[64][80];
    int h = blockIdx.x, b = blockIdx.y;
    int tid = threadIdx.x, tx = tid & 15, ty = tid >> 4;
    const float* kp = kbuf + ((size_t)(b*512 + h*64))*77;
    const float* vp = vbuf + ((size_t)(b*512 + h*64))*77;
    for (int idx = tid; idx < 64*80; idx += 256){
        int r = idx / 80, c = idx - r*80;
        float kv = (c < 77) ? kp[(size_t)r*77 + c] : 0.f;
        float vv = (c < 77) ? vp[(size_t)r*77 + c] : 0.f;
        ks[r][c] = kv; vs[r][c] = vv;
    }
    __syncthreads();
    // per-row softmax over n (77) on the k tile
    if (tid < 64){
        float m = -1e30f;
        for (int n = 0; n < 77; n++) m = fmaxf(m, ks[tid][n]);
        float s = 0.f;
        for (int n = 0; n < 77; n++){ float e = __expf(ks[tid][n] - m); ks[tid][n] = e; s += e; }
        float inv = 1.f / s;
        for (int n = 0; n < 77; n++) ks[tid][n] *= inv;
    }
    __syncthreads();
    float acc[4][4];
    #pragma unroll
    for (int i = 0; i < 4; i++)
        #pragma unroll
        for (int j = 0; j < 4; j++) acc[i][j] = 0.f;
    for (int n = 0; n < 77; n++){
        float a[4], c4[4];
        #pragma unroll
        for (int i = 0; i < 4; i++) a[i] = ks[ty*4 + i][n];
        #pragma unroll
        for (int j = 0; j < 4; j++) c4[j] = vs[tx*4 + j][n];
        #pragma unroll
        for (int i = 0; i < 4; i++)
            #pragma unroll
            for (int j = 0; j < 4; j++) acc[i][j] = fmaf(a[i], c4[j], acc[i][j]);
    }
    #pragma unroll
    for (int i = 0; i < 4; i++)
        #pragma unroll
        for (int j = 0; j < 4; j++)
            g_attn[(((size_t)(b*8 + h))*64 + ty*4 + i)*64 + tx*4 + j] = acc[i][j];
}

// ---------------- launch ----------------------------------------------------
extern "C" void kernel_launch(void* const* d_in, const int* in_sizes, int n_in,
                              void* d_out, int out_size){
    const float* x       = (const float*)d_in[0];
    const float* t       = (const float*)d_in[1];
    const float* cond    = (const float*)d_in[2];
    const float* conv0_w = (const float*)d_in[3];
    const float* conv0_b = (const float*)d_in[4];
    const float* gn0_g   = (const float*)d_in[5];
    const float* gn0_b   = (const float*)d_in[6];
    const float* tm_w    = (const float*)d_in[7];
    const float* tm_b    = (const float*)d_in[8];
    const float* conv1_w = (const float*)d_in[9];
    const float* conv1_b = (const float*)d_in[10];
    const float* gn1_g   = (const float*)d_in[11];
    const float* gn1_b   = (const float*)d_in[12];
    const float* res_w   = (const float*)d_in[13];
    const float* res_b   = (const float*)d_in[14];
    const float* ln_x_g  = (const float*)d_in[15];
    const float* ln_x_b  = (const float*)d_in[16];
    const float* ln_c_g  = (const float*)d_in[17];
    const float* ln_c_b  = (const float*)d_in[18];
    const float* q_w     = (const float*)d_in[19];
    const float* q_b     = (const float*)d_in[20];
    const float* k_w     = (const float*)d_in[21];
    const float* k_b     = (const float*)d_in[22];
    const float* v_w     = (const float*)d_in[23];
    const float* v_b     = (const float*)d_in[24];
    const int*   cidx    = (const int*)d_in[25];
    float* out = (float*)d_out;

    unsigned short *p_xt, *p_h2, *p_xln, *p_cn;
    uint32_t *p_w0, *p_w1, *p_wr, *p_wq, *p_wk, *p_wv;
    float *p_k, *p_v;
    cudaGetSymbolAddress((void**)&p_xt,  g_xt);
    cudaGetSymbolAddress((void**)&p_h2,  g_h2);
    cudaGetSymbolAddress((void**)&p_xln, g_xln);
    cudaGetSymbolAddress((void**)&p_cn,  g_cn);
    cudaGetSymbolAddress((void**)&p_k,   g_k);
    cudaGetSymbolAddress((void**)&p_v,   g_v);
    cudaGetSymbolAddress((void**)&p_w0,  g_w0);
    cudaGetSymbolAddress((void**)&p_w1,  g_w1);
    cudaGetSymbolAddress((void**)&p_wr,  g_wr);
    cudaGetSymbolAddress((void**)&p_wq,  g_wq);
    cudaGetSymbolAddress((void**)&p_wk,  g_wk);
    cudaGetSymbolAddress((void**)&p_wv,  g_wv);

    // smem (bytes)
    const int smem5 = 3*((132*12) + 2560)*4;  // 49728 (5-tap, 3 stages)
    const int smemE = 64*132*4;               // 33792 (MODE1/2 epilogue floor)
    const int smem1 = 3*((128*12) + 512)*4;   // 24576 (1-tap, 3 stages)
    const int smemY = (64*132 + 64*68)*4;     // 51200 (MODE3: et + attn tile)
    const int smA   = smem5 > smemE ? smem5 : smemE;
    const int smQ   = smem1 > smemY ? smem1 : smemY;
    const int smXLN = 64*513*4;               // 131328
    cudaFuncSetAttribute(k_conv<256,5,2,1>, cudaFuncAttributeMaxDynamicSharedMemorySize, smA);
    cudaFuncSetAttribute(k_conv<512,5,2,2>, cudaFuncAttributeMaxDynamicSharedMemorySize, smA);
    cudaFuncSetAttribute(k_conv<512,1,0,3>, cudaFuncAttributeMaxDynamicSharedMemorySize, smQ);
    cudaFuncSetAttribute(k_xln, cudaFuncAttributeMaxDynamicSharedMemorySize, smXLN);

    // mega producer: xpose | wprep(all) | ss | cn
    k_prod<<<13952, 256>>>(x, t, tm_w, tm_b, cond, ln_c_g, ln_c_b, cidx,
                           conv0_w, conv1_w, res_w, q_w, k_w, v_w);

    // cond chain
    k_conv<768,1,0,0><<<dim3(1,8,64), 256, smem1>>>(p_cn, p_wk, k_b, p_k, 77, nullptr, nullptr, nullptr);
    k_conv<768,1,0,0><<<dim3(1,8,64), 256, smem1>>>(p_cn, p_wv, v_b, p_v, 77, nullptr, nullptr, nullptr);
    k_attn<<<dim3(8,64), 256>>>(p_k, p_v);

    // main chain
    k_conv<256,1,0,0><<<dim3(4,8,64), 256, smem1>>>(p_xt, p_wr, res_b, out, 512, nullptr, nullptr, nullptr);
    k_conv<256,5,2,1><<<dim3(4,8,64), 256, smA>>>(p_xt, p_w0, conv0_b, (float*)p_h2, 512, gn0_g, gn0_b, nullptr);
    k_conv<512,5,2,2><<<dim3(4,8,64), 256, smA>>>(p_h2, p_w1, conv1_b, out, 512, gn1_g, gn1_b, nullptr);
    k_xln<<<dim3(8,64), 256, smXLN>>>(out, ln_x_g, ln_x_b, cidx, p_xln);
    // q proj + softmax + y = q@attn, RMW into out
    k_conv<512,1,0,3><<<dim3(4,8,64), 256, smQ>>>(p_xln, p_wq, q_b, out, 512, nullptr, nullptr, cidx);
}

// round 15
// speedup vs baseline: 1.2582x; 1.2582x over previous
#include <cuda_runtime.h>
#include <cuda_fp16.h>
#include <math.h>
#include <stdint.h>

#define EPSV 1e-5f

// ---------------- scratch (allocation-free: device globals) ----------------
__device__ float    g_ss  [64*1024];
__device__ unsigned short g_xt [64*512*256];   // fp16 x, [b][l][ci]
__device__ unsigned short g_h2 [64*512*512];   // fp16 conv0 out, [b][l][co]
__device__ unsigned short g_xln[64*512*512];   // fp16 LN(out), [b][t][c]
__device__ unsigned short g_cn [64*77*768];    // fp16 LN(cond), [b][n][ci]
__device__ float    g_k   [64*512*77];
__device__ float    g_v   [64*512*77];
__device__ float    g_attn[64*8*64*64];
// fragment-permuted fp16 weight copies (u32 = half2 k-pairs)
__device__ uint32_t g_w0[512*256*5/2];
__device__ uint32_t g_w1[512*512*5/2];
__device__ uint32_t g_wr[512*256/2];
__device__ uint32_t g_wq[512*512/2];
__device__ uint32_t g_wk[512*768/2];
__device__ uint32_t g_wv[512*768/2];

// fast mish
__device__ __forceinline__ float mishf(float x){
    float xc = fminf(x, 15.f);
    float e  = __expf(xc);
    float u  = 1.f + e;
    float u2 = u * u;
    return x * __fdividef(u2 - 1.f, u2 + 1.f);
}

// ---------------- fp16 mma helpers ------------------------------------------
__device__ __forceinline__ void mma_f16(float* c, uint4 a, uint32_t b0, uint32_t b1){
    asm("mma.sync.aligned.m16n8k16.row.col.f32.f16.f16.f32 "
        "{%0,%1,%2,%3}, {%4,%5,%6,%7}, {%8,%9}, {%0,%1,%2,%3};"
        : "+f"(c[0]), "+f"(c[1]), "+f"(c[2]), "+f"(c[3])
        : "r"(a.x), "r"(a.y), "r"(a.z), "r"(a.w), "r"(b0), "r"(b1));
}
__device__ __forceinline__ void ldsm_x4(uint32_t &r0, uint32_t &r1, uint32_t &r2,
                                        uint32_t &r3, uint32_t addr){
    asm volatile("ldmatrix.sync.aligned.m8n8.x4.shared.b16 {%0,%1,%2,%3}, [%4];"
                 : "=r"(r0), "=r"(r1), "=r"(r2), "=r"(r3) : "r"(addr));
}

// ---------------- cp.async helpers -------------------------------------------
__device__ __forceinline__ void cp16p(uint32_t dst, const void* src, bool pred){
    int sz = pred ? 16 : 0;
    asm volatile("cp.async.cg.shared.global [%0], [%1], 16, %2;"
                 :: "r"(dst), "l"(src), "r"(sz));
}
__device__ __forceinline__ void cp16(uint32_t dst, const void* src){
    asm volatile("cp.async.cg.shared.global [%0], [%1], 16;" :: "r"(dst), "l"(src));
}
__device__ __forceinline__ void cp_commit(){
    asm volatile("cp.async.commit_group;");
}
template<int N>
__device__ __forceinline__ void cp_wait(){
    asm volatile("cp.async.wait_group %0;" :: "n"(N));
}

// ---------------- x transpose: [b][ci][l] f32 -> [b][l][ci] fp16 -------------
__global__ void k_xpose(const float* __restrict__ src, unsigned short* __restrict__ dst){
    __shared__ float t[32][33];
    int b = blockIdx.z;
    int c0 = blockIdx.y*32, l0 = blockIdx.x*32;
    int tx = threadIdx.x & 31, ty = threadIdx.x >> 5;
    #pragma unroll
    for (int i = ty; i < 32; i += 8)
        t[i][tx] = src[((size_t)b*256 + c0 + i)*512 + l0 + tx];
    __syncthreads();
    #pragma unroll
    for (int i = ty; i < 32; i += 8){
        __half h = __float2half(t[tx][i]);
        dst[((size_t)b*512 + l0 + i)*256 + c0 + tx] = *(unsigned short*)&h;
    }
}

// ---------------- all weight preps in one launch ------------------------------
__device__ __forceinline__ void wperm1(const float* __restrict__ w, uint32_t* __restrict__ dst,
                                       int f, int CIN, int TAPS){
    int NCH = CIN/16;
    int j    = f & 3;
    int rem  = f >> 2;
    int lane = rem & 31;  rem >>= 5;
    int tap  = rem % TAPS; rem /= TAPS;
    int s    = rem & 3;   rem >>= 2;
    int ch   = rem % NCH;
    int cb   = rem / NCH;
    int qr = lane >> 2, qc = lane & 3;
    int co = cb*64 + s*16 + qr + (j & 1)*8;
    int ci = ch*16 + 2*qc + (j >> 1)*8;
    float w0 = w[((size_t)co*CIN + ci    )*TAPS + tap];
    float w1 = w[((size_t)co*CIN + ci + 1)*TAPS + tap];
    __half2 h = __floats2half2_rn(w0, w1);
    dst[f] = *(uint32_t*)&h;
}
__global__ void k_wprep_all(const float* w0s, const float* w1s, const float* wrs,
                            const float* wqs, const float* wks, const float* wvs){
    const int n0 = 512*256*5/2, n1 = 512*512*5/2, n2 = 512*256/2;
    const int n3 = 512*512/2,   n4 = 512*768/2,   n5 = 512*768/2;
    const int c0 = n0, c1 = c0+n1, c2 = c1+n2, c3 = c2+n3, c4 = c3+n4, c5 = c4+n5;
    int i = blockIdx.x*256 + threadIdx.x;
    int stride = gridDim.x*256;
    for (; i < c5; i += stride){
        if      (i < c0) wperm1(w0s, g_w0, i,      256, 5);
        else if (i < c1) wperm1(w1s, g_w1, i - c0, 512, 5);
        else if (i < c2) wperm1(wrs, g_wr, i - c1, 256, 1);
        else if (i < c3) wperm1(wqs, g_wq, i - c2, 512, 1);
        else if (i < c4) wperm1(wks, g_wk, i - c3, 768, 1);
        else             wperm1(wvs, g_wv, i - c4, 768, 1);
    }
}

// ---------------- ss = mish(t) @ tm_w^T + tm_b -----------------------------
__global__ void k_ss(const float* __restrict__ t, const float* __restrict__ w,
                     const float* __restrict__ bias){
    __shared__ float tm[512];
    int b = blockIdx.x, tid = threadIdx.x;
    for (int i = tid; i < 512; i += 256) tm[i] = mishf(t[b*512 + i]);
    __syncthreads();
    for (int o = tid; o < 1024; o += 256){
        const float* wr = w + (size_t)o * 512;
        float acc = bias[o];
        #pragma unroll 8
        for (int i = 0; i < 512; i++) acc = fmaf(tm[i], wr[i], acc);
        g_ss[b*1024 + o] = acc;
    }
}

// ---------------- conv1d as implicit GEMM on fp16 tensor cores ---------------
// MODE 0: plain bias (fp32 out) | 1: +GN+FiLM+mish (fp16 [l][co] out)
// MODE 2: +GN+mish+res add (fp32) | 3: +softmax(64 rows) + y=q@attn RMW into out
template<int CIN, int TAPS, int PAD, int MODE>
__global__ void k_conv(const unsigned short* __restrict__ in, const uint32_t* __restrict__ w,
                       const float* __restrict__ bias, float* __restrict__ out, int L,
                       const float* __restrict__ gg, const float* __restrict__ gb,
                       const int* __restrict__ cidx){
    constexpr int NTILE = 128;
    constexpr int LWD = NTILE + TAPS - 1;
    constexpr int KST = 24;
    constexpr int XSU = LWD*(KST/2);
    constexpr int WSU = 512*TAPS;
    constexpr int CHUNK = XSU + WSU;
    constexpr int EST = 132;
    extern __shared__ __align__(16) uint32_t smu[];
    __shared__ float red0[256], red1[256];
    __shared__ float stA[128], stB[128];
    __shared__ float rg[64], rb[64], rsc[64], rsh[64];

    const int l0 = blockIdx.x*NTILE, co0 = blockIdx.y*64, b = blockIdx.z;
    const int COUT = gridDim.y*64;
    const int tid = threadIdx.x, lane = tid & 31, wid = tid >> 5;
    const int wn = wid*16;
    const int qr = lane >> 2, qc = lane & 3;
    const uint32_t smaddr = (uint32_t)__cvta_generic_to_shared(smu);
    const int NCH = CIN/16;

    float acc[4][2][4];
    #pragma unroll
    for (int s = 0; s < 4; s++)
        #pragma unroll
        for (int ni = 0; ni < 2; ni++)
            #pragma unroll
            for (int r = 0; r < 4; r++) acc[s][ni][r] = 0.f;

    const unsigned short* inb = in + (size_t)b*L*CIN;
    const uint32_t* wblk = w + ((size_t)blockIdx.y*NCH)*WSU;

    auto fill = [&](int ch){
        uint32_t base = smaddr + (uint32_t)(ch % 3)*CHUNK*4;
        const int ci0 = ch*16;
        for (int idx = tid; idx < LWD*2; idx += 256){
            int row = idx >> 1, part = idx & 1;
            int l = l0 + row - PAD;
            bool ok = (l >= 0 && l < L);
            const unsigned short* src = inb + (size_t)(ok ? l : 0)*CIN + ci0 + part*8;
            cp16p(base + (row*KST + part*8)*2, src, ok);
        }
        uint32_t wsA = base + XSU*4;
        const uint32_t* wchunk = wblk + (size_t)ch*WSU;
        for (int idx = tid; idx < WSU/4; idx += 256)
            cp16(wsA + idx*16, wchunk + idx*4);
    };

    fill(0); cp_commit();
    if (NCH > 1) fill(1);
    cp_commit();

    for (int ch = 0; ch < NCH; ch++){
        if (ch + 2 < NCH) fill(ch + 2);
        cp_commit();
        cp_wait<2>();
        __syncthreads();

        const uint32_t xs_b = smaddr + (uint32_t)(ch % 3)*CHUNK*4;
        const uint32_t* wp = smu + (ch % 3)*CHUNK + XSU;

        #pragma unroll
        for (int tap = 0; tap < TAPS; tap++){
            uint4 A[4];
            #pragma unroll
            for (int s = 0; s < 4; s++)
                A[s] = *(const uint4*)&wp[((s*TAPS + tap)*32 + lane)*4];
            int row = wn + tap + (lane & 7) + ((lane >> 4) << 3);
            uint32_t addr = xs_b + ((uint32_t)row*KST + ((lane >> 3) & 1)*8)*2;
            uint32_t b0, b1, b2, b3;
            ldsm_x4(b0, b1, b2, b3, addr);
            #pragma unroll
            for (int s = 0; s < 4; s++){
                mma_f16(acc[s][0], A[s], b0, b1);
                mma_f16(acc[s][1], A[s], b2, b3);
            }
        }
        __syncthreads();
    }

    if (MODE == 0){
        #pragma unroll
        for (int s = 0; s < 4; s++){
            int r0 = co0 + s*16 + qr;
            float b0 = bias[r0], b1 = bias[r0 + 8];
            #pragma unroll
            for (int ni = 0; ni < 2; ni++){
                int c0 = l0 + wn + ni*8 + 2*qc;
                float* C = acc[s][ni];
                if (((L & 1) == 0) && (c0 + 1) < L){
                    *(float2*)&out[((size_t)b*COUT + r0    )*L + c0] = make_float2(C[0]+b0, C[1]+b0);
                    *(float2*)&out[((size_t)b*COUT + r0 + 8)*L + c0] = make_float2(C[2]+b1, C[3]+b1);
                } else {
                    if (c0 < L){
                        out[((size_t)b*COUT + r0    )*L + c0] = C[0] + b0;
                        out[((size_t)b*COUT + r0 + 8)*L + c0] = C[2] + b1;
                    }
                    if (c0 + 1 < L){
                        out[((size_t)b*COUT + r0    )*L + c0 + 1] = C[1] + b0;
                        out[((size_t)b*COUT + r0 + 8)*L + c0 + 1] = C[3] + b1;
                    }
                }
            }
        }
        return;
    }

    float* et = (float*)smu;
    #pragma unroll
    for (int s = 0; s < 4; s++){
        int r0 = s*16 + qr;
        float b0 = bias[co0 + r0], b1 = bias[co0 + r0 + 8];
        #pragma unroll
        for (int ni = 0; ni < 2; ni++){
            int c0 = wn + ni*8 + 2*qc;
            float* C = acc[s][ni];
            *(float2*)&et[ r0     *EST + c0] = make_float2(C[0]+b0, C[1]+b0);
            *(float2*)&et[(r0 + 8)*EST + c0] = make_float2(C[2]+b1, C[3]+b1);
        }
    }
    if ((MODE == 1 || MODE == 2) && tid < 64){
        rg[tid] = gg[co0 + tid]; rb[tid] = gb[co0 + tid];
        if (MODE == 1){
            rsc[tid] = g_ss[b*1024 + co0 + tid];
            rsh[tid] = g_ss[b*1024 + 512 + co0 + tid];
        }
    }
    __syncthreads();

    const int c = tid & 127, half = tid >> 7;
    if (MODE == 1 || MODE == 2){
        float s = 0.f, q = 0.f;
        #pragma unroll
        for (int r = 0; r < 32; r++){
            float v = et[(half*32 + r)*EST + c];
            s += v; q += v*v;
        }
        red0[tid] = s; red1[tid] = q;
        __syncthreads();
        if (tid < 128){
            float S = red0[tid] + red0[tid + 128];
            float Q = red1[tid] + red1[tid + 128];
            float m = S * (1.f/64.f);
            stA[tid] = m;
            stB[tid] = rsqrtf(Q * (1.f/64.f) - m*m + EPSV);
        }
        __syncthreads();
    } else {
        float m = -1e30f;
        #pragma unroll
        for (int r = 0; r < 32; r++) m = fmaxf(m, et[(half*32 + r)*EST + c]);
        red0[tid] = m;
        __syncthreads();
        if (tid < 128) stA[tid] = fmaxf(red0[tid], red0[tid + 128]);
        __syncthreads();
        float s = 0.f;
        #pragma unroll
        for (int r = 0; r < 32; r++) s += __expf(et[(half*32 + r)*EST + c] - stA[c]);
        red1[tid] = s;
        __syncthreads();
        if (tid < 128) stB[tid] = 1.f / (red1[tid] + red1[tid + 128]);
        __syncthreads();
    }

    if (MODE == 1){
        unsigned short* oh = (unsigned short*)out;
        #pragma unroll 4
        for (int kk = 0; kk < 32; kk++){
            int idx = kk*256 + tid;
            int cc = idx >> 6, r = idx & 63;
            float v = et[r*EST + cc];
            v = (v - stA[cc]) * stB[cc] * rg[r] + rb[r];
            v = v * (1.f + rsc[r]) + rsh[r];
            __half h = __float2half(mishf(v));
            oh[((size_t)b*512 + l0 + cc)*COUT + co0 + r] = *(unsigned short*)&h;
        }
    } else if (MODE == 2){
        #pragma unroll 4
        for (int kk = 0; kk < 32; kk++){
            int idx = kk*256 + tid;
            int r = idx >> 7, cc = idx & 127;
            float v = et[r*EST + cc];
            size_t gidx = ((size_t)b*COUT + co0 + r)*L + l0 + cc;
            v = (v - stA[cc]) * stB[cc] * rg[r] + rb[r];
            out[gidx] = mishf(v) + out[gidx];
        }
    } else {
        float* asf = et + 64*EST;
        #pragma unroll 4
        for (int kk = 0; kk < 32; kk++){
            int idx = kk*256 + tid;
            int r = idx >> 7, cc = idx & 127;
            et[r*EST + cc] = __expf(et[r*EST + cc] - stA[cc]) * stB[cc];
        }
        const int h = blockIdx.y;
        for (int idx = tid; idx < 64*64; idx += 256){
            int r = idx >> 6, cc = idx & 63;
            asf[r*68 + cc] = g_attn[(((size_t)(b*8 + h))*64 + r)*64 + cc];
        }
        __syncthreads();

        const int tx = tid & 15, ty = tid >> 4;
        float yacc[4][8];
        #pragma unroll
        for (int i = 0; i < 4; i++)
            #pragma unroll
            for (int j = 0; j < 8; j++) yacc[i][j] = 0.f;
        for (int d = 0; d < 64; d++){
            float4 q0 = *(const float4*)&et[d*EST + tx*8];
            float4 q1 = *(const float4*)&et[d*EST + tx*8 + 4];
            float qr8[8] = {q0.x,q0.y,q0.z,q0.w,q1.x,q1.y,q1.z,q1.w};
            float ar[4];
            #pragma unroll
            for (int i = 0; i < 4; i++) ar[i] = asf[d*68 + ty*4 + i];
            #pragma unroll
            for (int i = 0; i < 4; i++)
                #pragma unroll
                for (int j = 0; j < 8; j++) yacc[i][j] = fmaf(ar[i], qr8[j], yacc[i][j]);
        }
        const int bi = cidx[b];
        #pragma unroll
        for (int i = 0; i < 4; i++){
            int chn = co0 + ty*4 + i;
            float* dst = &out[((size_t)bi*512 + chn)*512 + l0 + tx*8];
            float4 o0 = *(float4*)dst;
            float4 o1 = *(float4*)(dst + 4);
            o0.x += yacc[i][0]; o0.y += yacc[i][1]; o0.z += yacc[i][2]; o0.w += yacc[i][3];
            o1.x += yacc[i][4]; o1.y += yacc[i][5]; o1.z += yacc[i][6]; o1.w += yacc[i][7];
            *(float4*)dst = o0;
            *(float4*)(dst + 4) = o1;
        }
    }
}

// ---------------- LN over channels -> g_xln fp16 [b][t][c], single gmem read -
__global__ void k_xln(const float* __restrict__ out, const float* __restrict__ gg,
                      const float* __restrict__ gb, const int* __restrict__ cidx,
                      unsigned short* __restrict__ dst){
    extern __shared__ float cache[];
    __shared__ float sm_s[4][64], sm_q[4][64];
    __shared__ float m_[64], r_[64];
    __shared__ float sg[512], sb[512];
    int b = blockIdx.y, t0 = blockIdx.x*64;
    int bi = cidx[b];
    const float* src = out + (size_t)bi*512*512;
    int tid = threadIdx.x;
    int tl = tid & 63, seg = tid >> 6;
    for (int i = tid; i < 512; i += 256){ sg[i] = gg[i]; sb[i] = gb[i]; }
    float s = 0.f, q = 0.f;
    for (int c = seg; c < 512; c += 4){
        float v = src[(size_t)c*512 + t0 + tl];
        cache[tl*513 + c] = v;
        s += v; q += v*v;
    }
    sm_s[seg][tl] = s; sm_q[seg][tl] = q;
    __syncthreads();
    if (tid < 64){
        float S = sm_s[0][tid]+sm_s[1][tid]+sm_s[2][tid]+sm_s[3][tid];
        float Q = sm_q[0][tid]+sm_q[1][tid]+sm_q[2][tid]+sm_q[3][tid];
        float m = S * (1.f/512.f);
        m_[tid] = m;
        r_[tid] = rsqrtf(Q * (1.f/512.f) - m*m + EPSV);
    }
    __syncthreads();
    for (int idx = tid; idx < 64*512; idx += 256){
        int t = idx >> 9, c = idx & 511;
        float v = cache[t*513 + c];
        __half h = __float2half((v - m_[t]) * r_[t] * sg[c] + sb[c]);
        dst[((size_t)b*512 + t0 + t)*512 + c] = *(unsigned short*)&h;
    }
}

// ---------------- LN(cond) -> g_cn fp16 [b][n][ci] ---------------------------
__global__ void k_cn(const float* __restrict__ cond, const float* __restrict__ gg,
                     const float* __restrict__ gb, const int* __restrict__ cidx){
    __shared__ float row[768];
    __shared__ float wsum[8], wsq[8];
    int n = blockIdx.x, b = blockIdx.y;
    int bi = cidx[b];
    int tid = threadIdx.x, lane = tid & 31, w = tid >> 5;
    const float* src = cond + ((size_t)bi*77 + n)*768;
    float s = 0.f, q = 0.f;
    for (int i = tid; i < 768; i += 256){ float v = src[i]; row[i] = v; s += v; q += v*v; }
    #pragma unroll
    for (int o = 16; o; o >>= 1){ s += __shfl_xor_sync(0xffffffffu, s, o); q += __shfl_xor_sync(0xffffffffu, q, o); }
    if (lane == 0){ wsum[w] = s; wsq[w] = q; }
    __syncthreads();
    if (tid == 0){
        float S = 0.f, Q = 0.f;
        #pragma unroll
        for (int i = 0; i < 8; i++){ S += wsum[i]; Q += wsq[i]; }
        float m = S * (1.f/768.f); float var = Q * (1.f/768.f) - m*m;
        wsum[0] = m; wsq[0] = rsqrtf(var + EPSV);
    }
    __syncthreads();
    float m = wsum[0], r = wsq[0];
    for (int i = tid; i < 768; i += 256){
        __half h = __float2half((row[i] - m) * r * gg[i] + gb[i]);
        g_cn[((size_t)b*77 + n)*768 + i] = *(unsigned short*)&h;
    }
}

// ---------------- k softmax over n (77) at fixed (b,d) ----------------------
__global__ void k_ksm(float* __restrict__ kbuf){
    int b = blockIdx.x;
    int d = blockIdx.y*8 + (threadIdx.x >> 5);
    int lane = threadIdx.x & 31;
    float* row = kbuf + ((size_t)b*512 + d)*77;
    float v0 = row[lane];
    float v1 = row[lane + 32];
    bool has2 = (lane + 64) < 77;
    float v2 = has2 ? row[lane + 64] : -1e30f;
    float m = fmaxf(fmaxf(v0, v1), v2);
    #pragma unroll
    for (int o = 16; o; o >>= 1) m = fmaxf(m, __shfl_xor_sync(0xffffffffu, m, o));
    float e0 = __expf(v0 - m), e1 = __expf(v1 - m), e2 = has2 ? __expf(v2 - m) : 0.f;
    float s = e0 + e1 + e2;
    #pragma unroll
    for (int o = 16; o; o >>= 1) s += __shfl_xor_sync(0xffffffffu, s, o);
    float inv = 1.f / s;
    row[lane] = e0 * inv;
    row[lane + 32] = e1 * inv;
    if (has2) row[lane + 64] = e2 * inv;
}

// ---------------- attn[b,h,d,l] = sum_n k[b,hd+d,n] * v[b,hd+l,n] ------------
// stride 81 (was 80): kills the 16-way bank conflict on vs column loads
__global__ void k_attn(const float* __restrict__ kbuf, const float* __restrict__ vbuf){
    __shared__ float ks[64][81], vs[64][81];
    int h = blockIdx.x, b = blockIdx.y;
    int tid = threadIdx.x, tx = tid & 15, ty = tid >> 4;
    const float* kp = kbuf + ((size_t)(b*512 + h*64))*77;
    const float* vp = vbuf + ((size_t)(b*512 + h*64))*77;
    for (int idx = tid; idx < 64*80; idx += 256){
        int r = idx / 80, c = idx - r*80;
        float kv = (c < 77) ? kp[(size_t)r*77 + c] : 0.f;
        float vv = (c < 77) ? vp[(size_t)r*77 + c] : 0.f;
        ks[r][c] = kv; vs[r][c] = vv;
    }
    __syncthreads();
    float acc[4][4];
    #pragma unroll
    for (int i = 0; i < 4; i++)
        #pragma unroll
        for (int j = 0; j < 4; j++) acc[i][j] = 0.f;
    #pragma unroll 7
    for (int n = 0; n < 77; n++){
        float a[4], c4[4];
        #pragma unroll
        for (int i = 0; i < 4; i++) a[i] = ks[ty*4 + i][n];
        #pragma unroll
        for (int j = 0; j < 4; j++) c4[j] = vs[tx*4 + j][n];
        #pragma unroll
        for (int i = 0; i < 4; i++)
            #pragma unroll
            for (int j = 0; j < 4; j++) acc[i][j] = fmaf(a[i], c4[j], acc[i][j]);
    }
    #pragma unroll
    for (int i = 0; i < 4; i++)
        #pragma unroll
        for (int j = 0; j < 4; j++)
            g_attn[(((size_t)(b*8 + h))*64 + ty*4 + i)*64 + tx*4 + j] = acc[i][j];
}

// ---------------- launch ----------------------------------------------------
extern "C" void kernel_launch(void* const* d_in, const int* in_sizes, int n_in,
                              void* d_out, int out_size){
    const float* x       = (const float*)d_in[0];
    const float* t       = (const float*)d_in[1];
    const float* cond    = (const float*)d_in[2];
    const float* conv0_w = (const float*)d_in[3];
    const float* conv0_b = (const float*)d_in[4];
    const float* gn0_g   = (const float*)d_in[5];
    const float* gn0_b   = (const float*)d_in[6];
    const float* tm_w    = (const float*)d_in[7];
    const float* tm_b    = (const float*)d_in[8];
    const float* conv1_w = (const float*)d_in[9];
    const float* conv1_b = (const float*)d_in[10];
    const float* gn1_g   = (const float*)d_in[11];
    const float* gn1_b   = (const float*)d_in[12];
    const float* res_w   = (const float*)d_in[13];
    const float* res_b   = (const float*)d_in[14];
    const float* ln_x_g  = (const float*)d_in[15];
    const float* ln_x_b  = (const float*)d_in[16];
    const float* ln_c_g  = (const float*)d_in[17];
    const float* ln_c_b  = (const float*)d_in[18];
    const float* q_w     = (const float*)d_in[19];
    const float* q_b     = (const float*)d_in[20];
    const float* k_w     = (const float*)d_in[21];
    const float* k_b     = (const float*)d_in[22];
    const float* v_w     = (const float*)d_in[23];
    const float* v_b     = (const float*)d_in[24];
    const int*   cidx    = (const int*)d_in[25];
    float* out = (float*)d_out;

    unsigned short *p_xt, *p_h2, *p_xln, *p_cn;
    uint32_t *p_w0, *p_w1, *p_wr, *p_wq, *p_wk, *p_wv;
    float *p_k, *p_v;
    cudaGetSymbolAddress((void**)&p_xt,  g_xt);
    cudaGetSymbolAddress((void**)&p_h2,  g_h2);
    cudaGetSymbolAddress((void**)&p_xln, g_xln);
    cudaGetSymbolAddress((void**)&p_cn,  g_cn);
    cudaGetSymbolAddress((void**)&p_k,   g_k);
    cudaGetSymbolAddress((void**)&p_v,   g_v);
    cudaGetSymbolAddress((void**)&p_w0,  g_w0);
    cudaGetSymbolAddress((void**)&p_w1,  g_w1);
    cudaGetSymbolAddress((void**)&p_wr,  g_wr);
    cudaGetSymbolAddress((void**)&p_wq,  g_wq);
    cudaGetSymbolAddress((void**)&p_wk,  g_wk);
    cudaGetSymbolAddress((void**)&p_wv,  g_wv);

    // smem (bytes)
    const int smem5 = 3*((132*12) + 2560)*4;  // 49728 (5-tap, 3 stages)
    const int smemE = 64*132*4;               // 33792 (MODE1/2 epilogue floor)
    const int smem1 = 3*((128*12) + 512)*4;   // 24576 (1-tap, 3 stages)
    const int smemY = (64*132 + 64*68)*4;     // 51200 (MODE3: et + attn tile)
    const int smA   = smem5 > smemE ? smem5 : smemE;
    const int smQ   = smem1 > smemY ? smem1 : smemY;
    const int smXLN = 64*513*4;               // 131328
    cudaFuncSetAttribute(k_conv<256,5,2,1>, cudaFuncAttributeMaxDynamicSharedMemorySize, smA);
    cudaFuncSetAttribute(k_conv<512,5,2,2>, cudaFuncAttributeMaxDynamicSharedMemorySize, smA);
    cudaFuncSetAttribute(k_conv<512,1,0,3>, cudaFuncAttributeMaxDynamicSharedMemorySize, smQ);
    cudaFuncSetAttribute(k_xln, cudaFuncAttributeMaxDynamicSharedMemorySize, smXLN);

    // producers (R12 structure)
    k_xpose<<<dim3(16,8,64), 256>>>(x, p_xt);
    k_wprep_all<<<768, 256>>>(conv0_w, conv1_w, res_w, q_w, k_w, v_w);
    k_ss<<<64, 256>>>(t, tm_w, tm_b);

    // cond chain
    k_cn<<<dim3(77,64), 256>>>(cond, ln_c_g, ln_c_b, cidx);
    k_conv<768,1,0,0><<<dim3(1,8,64), 256, smem1>>>(p_cn, p_wk, k_b, p_k, 77, nullptr, nullptr, nullptr);
    k_conv<768,1,0,0><<<dim3(1,8,64), 256, smem1>>>(p_cn, p_wv, v_b, p_v, 77, nullptr, nullptr, nullptr);
    k_ksm<<<dim3(64,64), 256>>>(p_k);
    k_attn<<<dim3(8,64), 256>>>(p_k, p_v);

    // main chain
    k_conv<256,1,0,0><<<dim3(4,8,64), 256, smem1>>>(p_xt, p_wr, res_b, out, 512, nullptr, nullptr, nullptr);
    k_conv<256,5,2,1><<<dim3(4,8,64), 256, smA>>>(p_xt, p_w0, conv0_b, (float*)p_h2, 512, gn0_g, gn0_b, nullptr);
    k_conv<512,5,2,2><<<dim3(4,8,64), 256, smA>>>(p_h2, p_w1, conv1_b, out, 512, gn1_g, gn1_b, nullptr);
    k_xln<<<dim3(8,64), 256, smXLN>>>(out, ln_x_g, ln_x_b, cidx, p_xln);
    // q proj + softmax + y = q@attn, RMW into out
    k_conv<512,1,0,3><<<dim3(4,8,64), 256, smQ>>>(p_xln, p_wq, q_b, out, 512, nullptr, nullptr, cidx);
}

// round 16
// speedup vs baseline: 1.3229x; 1.0514x over previous
#include <cuda_runtime.h>
#include <cuda_fp16.h>
#include <math.h>
#include <stdint.h>

#define EPSV 1e-5f

// ---------------- scratch (allocation-free: device globals) ----------------
__device__ float    g_ss  [64*1024];
__device__ unsigned short g_xt [64*512*256];   // fp16 x, [b][l][ci]
__device__ unsigned short g_h2 [64*512*512];   // fp16 conv0 out, [b][l][co]
__device__ unsigned short g_xln[64*512*512];   // fp16 LN(out), [b][t][c]
__device__ unsigned short g_cn [64*77*768];    // fp16 LN(cond), [b][n][ci]
__device__ float    g_k   [64*512*77];
__device__ float    g_v   [64*512*77];
__device__ float    g_attn[64*8*64*64];
// fragment-permuted fp16 weight copies (u32 = half2 k-pairs)
__device__ uint32_t g_w0[512*256*5/2];
__device__ uint32_t g_w1[512*512*5/2];
__device__ uint32_t g_wr[512*256/2];
__device__ uint32_t g_wq[512*512/2];
__device__ uint32_t g_wk[512*768/2];
__device__ uint32_t g_wv[512*768/2];

// fast mish
__device__ __forceinline__ float mishf(float x){
    float xc = fminf(x, 15.f);
    float e  = __expf(xc);
    float u  = 1.f + e;
    float u2 = u * u;
    return x * __fdividef(u2 - 1.f, u2 + 1.f);
}

// ---------------- fp16 mma helpers ------------------------------------------
__device__ __forceinline__ void mma_f16(float* c, uint4 a, uint32_t b0, uint32_t b1){
    asm("mma.sync.aligned.m16n8k16.row.col.f32.f16.f16.f32 "
        "{%0,%1,%2,%3}, {%4,%5,%6,%7}, {%8,%9}, {%0,%1,%2,%3};"
        : "+f"(c[0]), "+f"(c[1]), "+f"(c[2]), "+f"(c[3])
        : "r"(a.x), "r"(a.y), "r"(a.z), "r"(a.w), "r"(b0), "r"(b1));
}
__device__ __forceinline__ void ldsm_x4(uint32_t &r0, uint32_t &r1, uint32_t &r2,
                                        uint32_t &r3, uint32_t addr){
    asm volatile("ldmatrix.sync.aligned.m8n8.x4.shared.b16 {%0,%1,%2,%3}, [%4];"
                 : "=r"(r0), "=r"(r1), "=r"(r2), "=r"(r3) : "r"(addr));
}

// ---------------- cp.async helpers -------------------------------------------
__device__ __forceinline__ void cp16p(uint32_t dst, const void* src, bool pred){
    int sz = pred ? 16 : 0;
    asm volatile("cp.async.cg.shared.global [%0], [%1], 16, %2;"
                 :: "r"(dst), "l"(src), "r"(sz));
}
__device__ __forceinline__ void cp16(uint32_t dst, const void* src){
    asm volatile("cp.async.cg.shared.global [%0], [%1], 16;" :: "r"(dst), "l"(src));
}
__device__ __forceinline__ void cp_commit(){
    asm volatile("cp.async.commit_group;");
}
template<int N>
__device__ __forceinline__ void cp_wait(){
    asm volatile("cp.async.wait_group %0;" :: "n"(N));
}

// ---------------- x transpose: [b][ci][l] f32 -> [b][l][ci] fp16 -------------
__global__ void k_xpose(const float* __restrict__ src, unsigned short* __restrict__ dst){
    __shared__ float t[32][33];
    int b = blockIdx.z;
    int c0 = blockIdx.y*32, l0 = blockIdx.x*32;
    int tx = threadIdx.x & 31, ty = threadIdx.x >> 5;
    #pragma unroll
    for (int i = ty; i < 32; i += 8)
        t[i][tx] = src[((size_t)b*256 + c0 + i)*512 + l0 + tx];
    __syncthreads();
    #pragma unroll
    for (int i = ty; i < 32; i += 8){
        __half h = __float2half(t[tx][i]);
        dst[((size_t)b*512 + l0 + i)*256 + c0 + tx] = *(unsigned short*)&h;
    }
}

// ---------------- all weight preps in one launch ------------------------------
__device__ __forceinline__ void wperm1(const float* __restrict__ w, uint32_t* __restrict__ dst,
                                       int f, int CIN, int TAPS){
    int NCH = CIN/16;
    int j    = f & 3;
    int rem  = f >> 2;
    int lane = rem & 31;  rem >>= 5;
    int tap  = rem % TAPS; rem /= TAPS;
    int s    = rem & 3;   rem >>= 2;
    int ch   = rem % NCH;
    int cb   = rem / NCH;
    int qr = lane >> 2, qc = lane & 3;
    int co = cb*64 + s*16 + qr + (j & 1)*8;
    int ci = ch*16 + 2*qc + (j >> 1)*8;
    float w0 = w[((size_t)co*CIN + ci    )*TAPS + tap];
    float w1 = w[((size_t)co*CIN + ci + 1)*TAPS + tap];
    __half2 h = __floats2half2_rn(w0, w1);
    dst[f] = *(uint32_t*)&h;
}
__global__ void k_wprep_all(const float* w0s, const float* w1s, const float* wrs,
                            const float* wqs, const float* wks, const float* wvs){
    const int n0 = 512*256*5/2, n1 = 512*512*5/2, n2 = 512*256/2;
    const int n3 = 512*512/2,   n4 = 512*768/2,   n5 = 512*768/2;
    const int c0 = n0, c1 = c0+n1, c2 = c1+n2, c3 = c2+n3, c4 = c3+n4, c5 = c4+n5;
    int i = blockIdx.x*256 + threadIdx.x;
    int stride = gridDim.x*256;
    for (; i < c5; i += stride){
        if      (i < c0) wperm1(w0s, g_w0, i,      256, 5);
        else if (i < c1) wperm1(w1s, g_w1, i - c0, 512, 5);
        else if (i < c2) wperm1(wrs, g_wr, i - c1, 256, 1);
        else if (i < c3) wperm1(wqs, g_wq, i - c2, 512, 1);
        else if (i < c4) wperm1(wks, g_wk, i - c3, 768, 1);
        else             wperm1(wvs, g_wv, i - c4, 768, 1);
    }
}

// ---------------- ss = mish(t) @ tm_w^T + tm_b -----------------------------
__global__ void k_ss(const float* __restrict__ t, const float* __restrict__ w,
                     const float* __restrict__ bias){
    __shared__ float tm[512];
    int b = blockIdx.x, tid = threadIdx.x;
    for (int i = tid; i < 512; i += 256) tm[i] = mishf(t[b*512 + i]);
    __syncthreads();
    for (int o = tid; o < 1024; o += 256){
        const float* wr = w + (size_t)o * 512;
        float acc = bias[o];
        #pragma unroll 8
        for (int i = 0; i < 512; i++) acc = fmaf(tm[i], wr[i], acc);
        g_ss[b*1024 + o] = acc;
    }
}

// ---------------- conv1d as implicit GEMM on fp16 tensor cores ---------------
// MODE 0: plain bias (fp32 out) | 1: +GN+FiLM+mish (fp16 [l][co] out)
// MODE 2: +GN+mish+res add (fp32) | 3: +softmax(64 rows) + y=q@attn RMW into out
template<int CIN, int TAPS, int PAD, int MODE>
__global__ void k_conv(const unsigned short* __restrict__ in, const uint32_t* __restrict__ w,
                       const float* __restrict__ bias, float* __restrict__ out, int L,
                       const float* __restrict__ gg, const float* __restrict__ gb,
                       const int* __restrict__ cidx){
    constexpr int NTILE = 128;
    constexpr int LWD = NTILE + TAPS - 1;
    constexpr int KST = 24;
    constexpr int XSU = LWD*(KST/2);
    constexpr int WSU = 512*TAPS;
    constexpr int CHUNK = XSU + WSU;
    constexpr int EST = 132;
    extern __shared__ __align__(16) uint32_t smu[];
    __shared__ float red0[256], red1[256];
    __shared__ float stA[128], stB[128];
    __shared__ float rg[64], rb[64], rsc[64], rsh[64];

    const int l0 = blockIdx.x*NTILE, co0 = blockIdx.y*64, b = blockIdx.z;
    const int COUT = gridDim.y*64;
    const int tid = threadIdx.x, lane = tid & 31, wid = tid >> 5;
    const int wn = wid*16;
    const int qr = lane >> 2, qc = lane & 3;
    const uint32_t smaddr = (uint32_t)__cvta_generic_to_shared(smu);
    const int NCH = CIN/16;

    float acc[4][2][4];
    #pragma unroll
    for (int s = 0; s < 4; s++)
        #pragma unroll
        for (int ni = 0; ni < 2; ni++)
            #pragma unroll
            for (int r = 0; r < 4; r++) acc[s][ni][r] = 0.f;

    const unsigned short* inb = in + (size_t)b*L*CIN;
    const uint32_t* wblk = w + ((size_t)blockIdx.y*NCH)*WSU;

    auto fill = [&](int ch){
        uint32_t base = smaddr + (uint32_t)(ch % 3)*CHUNK*4;
        const int ci0 = ch*16;
        for (int idx = tid; idx < LWD*2; idx += 256){
            int row = idx >> 1, part = idx & 1;
            int l = l0 + row - PAD;
            bool ok = (l >= 0 && l < L);
            const unsigned short* src = inb + (size_t)(ok ? l : 0)*CIN + ci0 + part*8;
            cp16p(base + (row*KST + part*8)*2, src, ok);
        }
        uint32_t wsA = base + XSU*4;
        const uint32_t* wchunk = wblk + (size_t)ch*WSU;
        for (int idx = tid; idx < WSU/4; idx += 256)
            cp16(wsA + idx*16, wchunk + idx*4);
    };

    fill(0); cp_commit();
    if (NCH > 1) fill(1);
    cp_commit();

    for (int ch = 0; ch < NCH; ch++){
        if (ch + 2 < NCH) fill(ch + 2);
        cp_commit();
        cp_wait<2>();
        __syncthreads();

        const uint32_t xs_b = smaddr + (uint32_t)(ch % 3)*CHUNK*4;
        const uint32_t* wp = smu + (ch % 3)*CHUNK + XSU;

        #pragma unroll
        for (int tap = 0; tap < TAPS; tap++){
            uint4 A[4];
            #pragma unroll
            for (int s = 0; s < 4; s++)
                A[s] = *(const uint4*)&wp[((s*TAPS + tap)*32 + lane)*4];
            int row = wn + tap + (lane & 7) + ((lane >> 4) << 3);
            uint32_t addr = xs_b + ((uint32_t)row*KST + ((lane >> 3) & 1)*8)*2;
            uint32_t b0, b1, b2, b3;
            ldsm_x4(b0, b1, b2, b3, addr);
            #pragma unroll
            for (int s = 0; s < 4; s++){
                mma_f16(acc[s][0], A[s], b0, b1);
                mma_f16(acc[s][1], A[s], b2, b3);
            }
        }
        __syncthreads();
    }

    if (MODE == 0){
        #pragma unroll
        for (int s = 0; s < 4; s++){
            int r0 = co0 + s*16 + qr;
            float b0 = bias[r0], b1 = bias[r0 + 8];
            #pragma unroll
            for (int ni = 0; ni < 2; ni++){
                int c0 = l0 + wn + ni*8 + 2*qc;
                float* C = acc[s][ni];
                if (((L & 1) == 0) && (c0 + 1) < L){
                    *(float2*)&out[((size_t)b*COUT + r0    )*L + c0] = make_float2(C[0]+b0, C[1]+b0);
                    *(float2*)&out[((size_t)b*COUT + r0 + 8)*L + c0] = make_float2(C[2]+b1, C[3]+b1);
                } else {
                    if (c0 < L){
                        out[((size_t)b*COUT + r0    )*L + c0] = C[0] + b0;
                        out[((size_t)b*COUT + r0 + 8)*L + c0] = C[2] + b1;
                    }
                    if (c0 + 1 < L){
                        out[((size_t)b*COUT + r0    )*L + c0 + 1] = C[1] + b0;
                        out[((size_t)b*COUT + r0 + 8)*L + c0 + 1] = C[3] + b1;
                    }
                }
            }
        }
        return;
    }

    float* et = (float*)smu;
    #pragma unroll
    for (int s = 0; s < 4; s++){
        int r0 = s*16 + qr;
        float b0 = bias[co0 + r0], b1 = bias[co0 + r0 + 8];
        #pragma unroll
        for (int ni = 0; ni < 2; ni++){
            int c0 = wn + ni*8 + 2*qc;
            float* C = acc[s][ni];
            *(float2*)&et[ r0     *EST + c0] = make_float2(C[0]+b0, C[1]+b0);
            *(float2*)&et[(r0 + 8)*EST + c0] = make_float2(C[2]+b1, C[3]+b1);
        }
    }
    if ((MODE == 1 || MODE == 2) && tid < 64){
        rg[tid] = gg[co0 + tid]; rb[tid] = gb[co0 + tid];
        if (MODE == 1){
            rsc[tid] = g_ss[b*1024 + co0 + tid];
            rsh[tid] = g_ss[b*1024 + 512 + co0 + tid];
        }
    }
    __syncthreads();

    const int c = tid & 127, half = tid >> 7;
    if (MODE == 1 || MODE == 2){
        float s = 0.f, q = 0.f;
        #pragma unroll
        for (int r = 0; r < 32; r++){
            float v = et[(half*32 + r)*EST + c];
            s += v; q += v*v;
        }
        red0[tid] = s; red1[tid] = q;
        __syncthreads();
        if (tid < 128){
            float S = red0[tid] + red0[tid + 128];
            float Q = red1[tid] + red1[tid + 128];
            float m = S * (1.f/64.f);
            stA[tid] = m;
            stB[tid] = rsqrtf(Q * (1.f/64.f) - m*m + EPSV);
        }
        __syncthreads();
    } else {
        float m = -1e30f;
        #pragma unroll
        for (int r = 0; r < 32; r++) m = fmaxf(m, et[(half*32 + r)*EST + c]);
        red0[tid] = m;
        __syncthreads();
        if (tid < 128) stA[tid] = fmaxf(red0[tid], red0[tid + 128]);
        __syncthreads();
        float s = 0.f;
        #pragma unroll
        for (int r = 0; r < 32; r++) s += __expf(et[(half*32 + r)*EST + c] - stA[c]);
        red1[tid] = s;
        __syncthreads();
        if (tid < 128) stB[tid] = 1.f / (red1[tid] + red1[tid + 128]);
        __syncthreads();
    }

    if (MODE == 1){
        unsigned short* oh = (unsigned short*)out;
        #pragma unroll 4
        for (int kk = 0; kk < 32; kk++){
            int idx = kk*256 + tid;
            int cc = idx >> 6, r = idx & 63;
            float v = et[r*EST + cc];
            v = (v - stA[cc]) * stB[cc] * rg[r] + rb[r];
            v = v * (1.f + rsc[r]) + rsh[r];
            __half h = __float2half(mishf(v));
            oh[((size_t)b*512 + l0 + cc)*COUT + co0 + r] = *(unsigned short*)&h;
        }
    } else if (MODE == 2){
        #pragma unroll 4
        for (int kk = 0; kk < 32; kk++){
            int idx = kk*256 + tid;
            int r = idx >> 7, cc = idx & 127;
            float v = et[r*EST + cc];
            size_t gidx = ((size_t)b*COUT + co0 + r)*L + l0 + cc;
            v = (v - stA[cc]) * stB[cc] * rg[r] + rb[r];
            out[gidx] = mishf(v) + out[gidx];
        }
    } else {
        float* asf = et + 64*EST;
        #pragma unroll 4
        for (int kk = 0; kk < 32; kk++){
            int idx = kk*256 + tid;
            int r = idx >> 7, cc = idx & 127;
            et[r*EST + cc] = __expf(et[r*EST + cc] - stA[cc]) * stB[cc];
        }
        const int h = blockIdx.y;
        for (int idx = tid; idx < 64*64; idx += 256){
            int r = idx >> 6, cc = idx & 63;
            asf[r*68 + cc] = g_attn[(((size_t)(b*8 + h))*64 + r)*64 + cc];
        }
        __syncthreads();

        const int tx = tid & 15, ty = tid >> 4;
        float yacc[4][8];
        #pragma unroll
        for (int i = 0; i < 4; i++)
            #pragma unroll
            for (int j = 0; j < 8; j++) yacc[i][j] = 0.f;
        for (int d = 0; d < 64; d++){
            float4 q0 = *(const float4*)&et[d*EST + tx*8];
            float4 q1 = *(const float4*)&et[d*EST + tx*8 + 4];
            float qr8[8] = {q0.x,q0.y,q0.z,q0.w,q1.x,q1.y,q1.z,q1.w};
            float ar[4];
            #pragma unroll
            for (int i = 0; i < 4; i++) ar[i] = asf[d*68 + ty*4 + i];
            #pragma unroll
            for (int i = 0; i < 4; i++)
                #pragma unroll
                for (int j = 0; j < 8; j++) yacc[i][j] = fmaf(ar[i], qr8[j], yacc[i][j]);
        }
        const int bi = cidx[b];
        #pragma unroll
        for (int i = 0; i < 4; i++){
            int chn = co0 + ty*4 + i;
            float* dst = &out[((size_t)bi*512 + chn)*512 + l0 + tx*8];
            float4 o0 = *(float4*)dst;
            float4 o1 = *(float4*)(dst + 4);
            o0.x += yacc[i][0]; o0.y += yacc[i][1]; o0.z += yacc[i][2]; o0.w += yacc[i][3];
            o1.x += yacc[i][4]; o1.y += yacc[i][5]; o1.z += yacc[i][6]; o1.w += yacc[i][7];
            *(float4*)dst = o0;
            *(float4*)(dst + 4) = o1;
        }
    }
}

// ---------------- LN over channels -> g_xln fp16 [b][t][c] -------------------
// 32 t-rows per block (66 KB smem -> 3 CTAs/SM), single gmem read
__global__ void k_xln(const float* __restrict__ out, const float* __restrict__ gg,
                      const float* __restrict__ gb, const int* __restrict__ cidx,
                      unsigned short* __restrict__ dst){
    extern __shared__ float cache[];        // [32][513]
    __shared__ float sm_s[8][32], sm_q[8][32];
    __shared__ float m_[32], r_[32];
    __shared__ float sg[512], sb[512];
    int b = blockIdx.y, t0 = blockIdx.x*32;
    int bi = cidx[b];
    const float* src = out + (size_t)bi*512*512;
    int tid = threadIdx.x;
    int tl = tid & 31, seg = tid >> 5;
    for (int i = tid; i < 512; i += 256){ sg[i] = gg[i]; sb[i] = gb[i]; }
    float s = 0.f, q = 0.f;
    for (int c = seg; c < 512; c += 8){
        float v = src[(size_t)c*512 + t0 + tl];
        cache[tl*513 + c] = v;
        s += v; q += v*v;
    }
    sm_s[seg][tl] = s; sm_q[seg][tl] = q;
    __syncthreads();
    if (tid < 32){
        float S = 0.f, Q = 0.f;
        #pragma unroll
        for (int w = 0; w < 8; w++){ S += sm_s[w][tid]; Q += sm_q[w][tid]; }
        float m = S * (1.f/512.f);
        m_[tid] = m;
        r_[tid] = rsqrtf(Q * (1.f/512.f) - m*m + EPSV);
    }
    __syncthreads();
    for (int idx = tid; idx < 32*512; idx += 256){
        int t = idx >> 9, c = idx & 511;
        float v = cache[t*513 + c];
        __half h = __float2half((v - m_[t]) * r_[t] * sg[c] + sb[c]);
        dst[((size_t)b*512 + t0 + t)*512 + c] = *(unsigned short*)&h;
    }
}

// ---------------- LN(cond) -> g_cn fp16 [b][n][ci] ---------------------------
__global__ void k_cn(const float* __restrict__ cond, const float* __restrict__ gg,
                     const float* __restrict__ gb, const int* __restrict__ cidx){
    __shared__ float row[768];
    __shared__ float wsum[8], wsq[8];
    int n = blockIdx.x, b = blockIdx.y;
    int bi = cidx[b];
    int tid = threadIdx.x, lane = tid & 31, w = tid >> 5;
    const float* src = cond + ((size_t)bi*77 + n)*768;
    float s = 0.f, q = 0.f;
    for (int i = tid; i < 768; i += 256){ float v = src[i]; row[i] = v; s += v; q += v*v; }
    #pragma unroll
    for (int o = 16; o; o >>= 1){ s += __shfl_xor_sync(0xffffffffu, s, o); q += __shfl_xor_sync(0xffffffffu, q, o); }
    if (lane == 0){ wsum[w] = s; wsq[w] = q; }
    __syncthreads();
    if (tid == 0){
        float S = 0.f, Q = 0.f;
        #pragma unroll
        for (int i = 0; i < 8; i++){ S += wsum[i]; Q += wsq[i]; }
        float m = S * (1.f/768.f); float var = Q * (1.f/768.f) - m*m;
        wsum[0] = m; wsq[0] = rsqrtf(var + EPSV);
    }
    __syncthreads();
    float m = wsum[0], r = wsq[0];
    for (int i = tid; i < 768; i += 256){
        __half h = __float2half((row[i] - m) * r * gg[i] + gb[i]);
        g_cn[((size_t)b*77 + n)*768 + i] = *(unsigned short*)&h;
    }
}

// ---------------- k softmax over n (77) at fixed (b,d) ----------------------
__global__ void k_ksm(float* __restrict__ kbuf){
    int b = blockIdx.x;
    int d = blockIdx.y*8 + (threadIdx.x >> 5);
    int lane = threadIdx.x & 31;
    float* row = kbuf + ((size_t)b*512 + d)*77;
    float v0 = row[lane];
    float v1 = row[lane + 32];
    bool has2 = (lane + 64) < 77;
    float v2 = has2 ? row[lane + 64] : -1e30f;
    float m = fmaxf(fmaxf(v0, v1), v2);
    #pragma unroll
    for (int o = 16; o; o >>= 1) m = fmaxf(m, __shfl_xor_sync(0xffffffffu, m, o));
    float e0 = __expf(v0 - m), e1 = __expf(v1 - m), e2 = has2 ? __expf(v2 - m) : 0.f;
    float s = e0 + e1 + e2;
    #pragma unroll
    for (int o = 16; o; o >>= 1) s += __shfl_xor_sync(0xffffffffu, s, o);
    float inv = 1.f / s;
    row[lane] = e0 * inv;
    row[lane + 32] = e1 * inv;
    if (has2) row[lane + 64] = e2 * inv;
}

// ---------------- attn[b,h,d,l] = sum_n k[b,hd+d,n] * v[b,hd+l,n] ------------
// stride 81: conflict-free column loads
__global__ void k_attn(const float* __restrict__ kbuf, const float* __restrict__ vbuf){
    __shared__ float ks[64][81], vs[64][81];
    int h = blockIdx.x, b = blockIdx.y;
    int tid = threadIdx.x, tx = tid & 15, ty = tid >> 4;
    const float* kp = kbuf + ((size_t)(b*512 + h*64))*77;
    const float* vp = vbuf + ((size_t)(b*512 + h*64))*77;
    for (int idx = tid; idx < 64*80; idx += 256){
        int r = idx / 80, c = idx - r*80;
        float kv = (c < 77) ? kp[(size_t)r*77 + c] : 0.f;
        float vv = (c < 77) ? vp[(size_t)r*77 + c] : 0.f;
        ks[r][c] = kv; vs[r][c] = vv;
    }
    __syncthreads();
    float acc[4][4];
    #pragma unroll
    for (int i = 0; i < 4; i++)
        #pragma unroll
        for (int j = 0; j < 4; j++) acc[i][j] = 0.f;
    #pragma unroll 7
    for (int n = 0; n < 77; n++){
        float a[4], c4[4];
        #pragma unroll
        for (int i = 0; i < 4; i++) a[i] = ks[ty*4 + i][n];
        #pragma unroll
        for (int j = 0; j < 4; j++) c4[j] = vs[tx*4 + j][n];
        #pragma unroll
        for (int i = 0; i < 4; i++)
            #pragma unroll
            for (int j = 0; j < 4; j++) acc[i][j] = fmaf(a[i], c4[j], acc[i][j]);
    }
    #pragma unroll
    for (int i = 0; i < 4; i++)
        #pragma unroll
        for (int j = 0; j < 4; j++)
            g_attn[(((size_t)(b*8 + h))*64 + ty*4 + i)*64 + tx*4 + j] = acc[i][j];
}

// ---------------- launch ----------------------------------------------------
extern "C" void kernel_launch(void* const* d_in, const int* in_sizes, int n_in,
                              void* d_out, int out_size){
    const float* x       = (const float*)d_in[0];
    const float* t       = (const float*)d_in[1];
    const float* cond    = (const float*)d_in[2];
    const float* conv0_w = (const float*)d_in[3];
    const float* conv0_b = (const float*)d_in[4];
    const float* gn0_g   = (const float*)d_in[5];
    const float* gn0_b   = (const float*)d_in[6];
    const float* tm_w    = (const float*)d_in[7];
    const float* tm_b    = (const float*)d_in[8];
    const float* conv1_w = (const float*)d_in[9];
    const float* conv1_b = (const float*)d_in[10];
    const float* gn1_g   = (const float*)d_in[11];
    const float* gn1_b   = (const float*)d_in[12];
    const float* res_w   = (const float*)d_in[13];
    const float* res_b   = (const float*)d_in[14];
    const float* ln_x_g  = (const float*)d_in[15];
    const float* ln_x_b  = (const float*)d_in[16];
    const float* ln_c_g  = (const float*)d_in[17];
    const float* ln_c_b  = (const float*)d_in[18];
    const float* q_w     = (const float*)d_in[19];
    const float* q_b     = (const float*)d_in[20];
    const float* k_w     = (const float*)d_in[21];
    const float* k_b     = (const float*)d_in[22];
    const float* v_w     = (const float*)d_in[23];
    const float* v_b     = (const float*)d_in[24];
    const int*   cidx    = (const int*)d_in[25];
    float* out = (float*)d_out;

    unsigned short *p_xt, *p_h2, *p_xln, *p_cn;
    uint32_t *p_w0, *p_w1, *p_wr, *p_wq, *p_wk, *p_wv;
    float *p_k, *p_v;
    cudaGetSymbolAddress((void**)&p_xt,  g_xt);
    cudaGetSymbolAddress((void**)&p_h2,  g_h2);
    cudaGetSymbolAddress((void**)&p_xln, g_xln);
    cudaGetSymbolAddress((void**)&p_cn,  g_cn);
    cudaGetSymbolAddress((void**)&p_k,   g_k);
    cudaGetSymbolAddress((void**)&p_v,   g_v);
    cudaGetSymbolAddress((void**)&p_w0,  g_w0);
    cudaGetSymbolAddress((void**)&p_w1,  g_w1);
    cudaGetSymbolAddress((void**)&p_wr,  g_wr);
    cudaGetSymbolAddress((void**)&p_wq,  g_wq);
    cudaGetSymbolAddress((void**)&p_wk,  g_wk);
    cudaGetSymbolAddress((void**)&p_wv,  g_wv);

    // smem (bytes)
    const int smem5 = 3*((132*12) + 2560)*4;  // 49728 (5-tap, 3 stages)
    const int smemE = 64*132*4;               // 33792 (MODE1/2 epilogue floor)
    const int smem1 = 3*((128*12) + 512)*4;   // 24576 (1-tap, 3 stages)
    const int smemY = (64*132 + 64*68)*4;     // 51200 (MODE3: et + attn tile)
    const int smA   = smem5 > smemE ? smem5 : smemE;
    const int smQ   = smem1 > smemY ? smem1 : smemY;
    const int smXLN = 32*513*4;               // 65664
    cudaFuncSetAttribute(k_conv<256,5,2,1>, cudaFuncAttributeMaxDynamicSharedMemorySize, smA);
    cudaFuncSetAttribute(k_conv<512,5,2,2>, cudaFuncAttributeMaxDynamicSharedMemorySize, smA);
    cudaFuncSetAttribute(k_conv<512,1,0,3>, cudaFuncAttributeMaxDynamicSharedMemorySize, smQ);
    cudaFuncSetAttribute(k_xln, cudaFuncAttributeMaxDynamicSharedMemorySize, smXLN);

    // producers
    k_xpose<<<dim3(16,8,64), 256>>>(x, p_xt);
    k_wprep_all<<<768, 256>>>(conv0_w, conv1_w, res_w, q_w, k_w, v_w);
    k_ss<<<64, 256>>>(t, tm_w, tm_b);

    // cond chain
    k_cn<<<dim3(77,64), 256>>>(cond, ln_c_g, ln_c_b, cidx);
    k_conv<768,1,0,0><<<dim3(1,8,64), 256, smem1>>>(p_cn, p_wk, k_b, p_k, 77, nullptr, nullptr, nullptr);
    k_conv<768,1,0,0><<<dim3(1,8,64), 256, smem1>>>(p_cn, p_wv, v_b, p_v, 77, nullptr, nullptr, nullptr);
    k_ksm<<<dim3(64,64), 256>>>(p_k);
    k_attn<<<dim3(8,64), 256>>>(p_k, p_v);

    // main chain
    k_conv<256,1,0,0><<<dim3(4,8,64), 256, smem1>>>(p_xt, p_wr, res_b, out, 512, nullptr, nullptr, nullptr);
    k_conv<256,5,2,1><<<dim3(4,8,64), 256, smA>>>(p_xt, p_w0, conv0_b, (float*)p_h2, 512, gn0_g, gn0_b, nullptr);
    k_conv<512,5,2,2><<<dim3(4,8,64), 256, smA>>>(p_h2, p_w1, conv1_b, out, 512, gn1_g, gn1_b, nullptr);
    k_xln<<<dim3(16,64), 256, smXLN>>>(out, ln_x_g, ln_x_b, cidx, p_xln);
    // q proj + softmax + y = q@attn, RMW into out
    k_conv<512,1,0,3><<<dim3(4,8,64), 256, smQ>>>(p_xln, p_wq, q_b, out, 512, nullptr, nullptr, cidx);
}